// round 17
// baseline (speedup 1.0000x reference)
#include <cuda_runtime.h>
#include <cstdint>

#define NPTS   16384
#define NB     4
#define MPER   4096
#define NCENT  (NB*MPER)          // 16384 centroids
#define KNBR   33                 // K+1
#define NEDGE  (NCENT*KNBR)       // 540672 edges
#define H1DIM  128
#define H2DIM  256
#define CDIM   32
#define R2CONST 0.04f

#define OUT_POS_OFF   (NCENT*H2DIM)
#define OUT_BATCH_OFF (OUT_POS_OFF + NCENT*3)

typedef unsigned long long ull;

// -------------------- device scratch --------------------------------------
__device__ int      g_fps[NCENT];
__device__ int      g_gidx[NCENT];
__device__ float    g_cent[NCENT*3];
__device__ int      g_nbr[NEDGE];
__device__ int      g_sortidx[NB*NPTS];             // sorted slot -> original idx
__device__ float    g_A  [(size_t)NB*NPTS*H1DIM];
__device__ float    g_H1 [(size_t)NEDGE*H1DIM];
__device__ unsigned g_agg[(size_t)NCENT*H2DIM];     // segment max as uint bits

// -------------------- 1) bucketed FPS, register-resident M -----------------
// Exact-equivalent FPS: 8^3 grid, per-cell packed max keys
// (d2bits:32 | invOrig:14 | slot:14), conservative fma-consistent AABB
// pruning. Strided register ownership: thread tid owns slots tid+512k, so a
// dirty cell's points are spread one-per-thread across consecutive threads.
// Updates touch smem/registers only; cell keys rebuilt via smem atomicMax.
__device__ __forceinline__ int cellof(float x, float y, float z) {
    int ix = (int)(x * 8.0f); ix = ix < 0 ? 0 : (ix > 7 ? 7 : ix);
    int iy = (int)(y * 8.0f); iy = iy < 0 ? 0 : (iy > 7 ? 7 : iy);
    int iz = (int)(z * 8.0f); iz = iz < 0 ? 0 : (iz > 7 ? 7 : iz);
    return (iz << 6) | (iy << 3) | ix;
}

#define FPS_SMEM (3*NPTS*4 + 512*8 + 16*4)

__global__ void __launch_bounds__(512,1) fps_kernel(const float* __restrict__ pos) {
    int b = blockIdx.x;
    extern __shared__ float sm[];
    float* Xs = sm; float* Ys = sm + NPTS; float* Zs = sm + 2*NPTS;
    ull* cellkey = (ull*)(sm + 3*NPTS);              // 512 keys
    unsigned* dirtyw = (unsigned*)(cellkey + 512);   // 16-word dirty bitmap
    __shared__ int   cnt[512];
    __shared__ ull   warpmax[16];
    __shared__ int   warplist[16];
    __shared__ float qsh[3];
    __shared__ int   nw_sh;
    int tid = threadIdx.x, lane = tid & 31, wid = tid >> 5;
    const float* p = pos + (size_t)b*NPTS*3;
    int* gO = g_sortidx + (size_t)b*NPTS;

    cnt[tid] = 0;
    cellkey[tid] = 0ull;
    __syncthreads();

    // count points per cell
    for (int i = tid; i < NPTS; i += 512)
        atomicAdd(&cnt[cellof(p[3*i], p[3*i+1], p[3*i+2])], 1);
    __syncthreads();

    // exclusive prefix sum over 512 counts (warp 0) -> cnt = start ptrs
    if (wid == 0) {
        int carry = 0;
        for (int cc = 0; cc < 16; cc++) {
            int v0 = cnt[cc*32 + lane];
            int v = v0;
#pragma unroll
            for (int off = 1; off < 32; off <<= 1) {
                int o = __shfl_up_sync(0xffffffffu, v, off);
                if (lane >= off) v += o;
            }
            int tot = __shfl_sync(0xffffffffu, v, 31);
            cnt[cc*32 + lane] = v - v0 + carry;
            carry += tot;
        }
    }
    __syncthreads();

    // scatter into sorted order
    for (int i = tid; i < NPTS; i += 512) {
        float x = p[3*i], y = p[3*i+1], z = p[3*i+2];
        int c = cellof(x, y, z);
        int s = atomicAdd(&cnt[c], 1);
        Xs[s] = x; Ys[s] = y; Zs[s] = z;
        gO[s] = i;
    }
    if (tid == 0) g_fps[b*MPER] = 0;
    __syncthreads();

    // per-thread strided ownership: slots tid + 512k
    float    M[32];
    unsigned cid16[16], org16[16];
#pragma unroll
    for (int k = 0; k < 16; k++) { cid16[k] = 0u; org16[k] = 0u; }
    float q0x = p[0], q0y = p[1], q0z = p[2];
#pragma unroll
    for (int k = 0; k < 32; k++) {
        int s = tid + (k << 9);
        int o = gO[s];
        float x = Xs[s], y = Ys[s], z = Zs[s];
        int c = cellof(x, y, z);
        cid16[k >> 1] |= (unsigned)c << ((k & 1) * 16);
        org16[k >> 1] |= (unsigned)o << ((k & 1) * 16);
        float dx = x - q0x, dy = y - q0y, dz = z - q0z;
        float d2 = fmaf(dz, dz, fmaf(dy, dy, dx*dx));
        M[k] = d2;
        ull key = ((ull)__float_as_uint(d2) << 32)
                | ((ull)(unsigned)(NPTS - 1 - o) << 14) | (unsigned)s;
        atomicMax(&cellkey[c], key);
    }
    __syncthreads();

    // initial warpmax
    {
        ull key = cellkey[tid];
#pragma unroll
        for (int off = 16; off > 0; off >>= 1) {
            ull o2 = __shfl_down_sync(0xffffffffu, key, off);
            if (o2 > key) key = o2;
        }
        if (lane == 0) warpmax[wid] = key;
    }
    __syncthreads();

    const float CS = 0.125f;
    float lox = (float)(tid & 7) * CS;
    float loy = (float)((tid >> 3) & 7) * CS;
    float loz = (float)(tid >> 6) * CS;
    float hix = lox + CS, hiy = loy + CS, hiz = loz + CS;

    for (int t = 1; t < MPER; t++) {
        // ---- A: argmax over 16 warp maxima (warp 0) ----
        if (wid == 0) {
            ull k2 = warpmax[lane & 15];
#pragma unroll
            for (int off = 8; off > 0; off >>= 1) {
                ull o2 = __shfl_down_sync(0xffffffffu, k2, off);
                if (o2 > k2) k2 = o2;
            }
            if (lane == 0) {
                int slot = (int)(k2 & 0x3FFFu);
                int orig = NPTS - 1 - (int)((k2 >> 14) & 0x3FFFu);
                g_fps[b*MPER + t] = orig;
                qsh[0] = Xs[slot]; qsh[1] = Ys[slot]; qsh[2] = Zs[slot];
                nw_sh = 0;
            }
        }
        __syncthreads();
        float qx = qsh[0], qy = qsh[1], qz = qsh[2];

        // ---- B: dirty cells (AABB lower bound, fma-consistent) ----
        ull mykey = cellkey[tid];
        float cm = __uint_as_float((unsigned)(mykey >> 32));
        float lbx = fmaxf(fmaxf(lox - qx, qx - hix), 0.0f);
        float lby = fmaxf(fmaxf(loy - qy, qy - hiy), 0.0f);
        float lbz = fmaxf(fmaxf(loz - qz, qz - hiz), 0.0f);
        float lb2 = fmaf(lbz, lbz, fmaf(lby, lby, lbx*lbx));
        bool d = (lb2 < cm);
        if (d) cellkey[tid] = 0ull;
        unsigned m = __ballot_sync(0xffffffffu, d);
        if (lane == 0) {
            dirtyw[wid] = m;
            if (m) warplist[atomicAdd(&nw_sh, 1)] = wid;
        }
        __syncthreads();
        int nw = nw_sh;

        // ---- C: per-thread register update of owned points ----
#pragma unroll
        for (int k = 0; k < 32; k++) {
            int c = (int)((cid16[k >> 1] >> ((k & 1) * 16)) & 0xFFFFu);
            unsigned w = dirtyw[c >> 5];
            if ((w >> (c & 31)) & 1u) {
                int s = tid + (k << 9);
                float dx = Xs[s]-qx, dy = Ys[s]-qy, dz = Zs[s]-qz;
                float d2 = fmaf(dz, dz, fmaf(dy, dy, dx*dx));
                float nm = fminf(M[k], d2);
                M[k] = nm;
                int o = (int)((org16[k >> 1] >> ((k & 1) * 16)) & 0xFFFFu);
                ull key = ((ull)__float_as_uint(nm) << 32)
                        | ((ull)(unsigned)(NPTS - 1 - o) << 14) | (unsigned)s;
                atomicMax(&cellkey[c], key);
            }
        }
        __syncthreads();

        // ---- D: recompute warpmax for warps containing dirty cells --------
        for (int j = wid; j < nw; j += 16) {
            int w = warplist[j];
            ull key = cellkey[(w << 5) + lane];
#pragma unroll
            for (int off = 16; off > 0; off >>= 1) {
                ull o2 = __shfl_down_sync(0xffffffffu, key, off);
                if (o2 > key) key = o2;
            }
            if (lane == 0) warpmax[w] = key;
        }
        __syncthreads();
    }
}

// -------------------- 2) gather centroids + write pos/batch outputs --------
__global__ void gather_kernel(const float* __restrict__ pos,
                              const int* __restrict__ batch,
                              float* __restrict__ dout) {
    int i = blockIdx.x*blockDim.x + threadIdx.x;
    if (i >= NCENT) return;
    int b = i >> 12;
    int sel = g_fps[i];
    int g = b*NPTS + sel;
    float x = pos[3*g], y = pos[3*g+1], z = pos[3*g+2];
    g_cent[3*i] = x; g_cent[3*i+1] = y; g_cent[3*i+2] = z;
    g_gidx[i] = g;
    dout[OUT_POS_OFF + 3*i]   = x;
    dout[OUT_POS_OFF + 3*i+1] = y;
    dout[OUT_POS_OFF + 3*i+2] = z;
    dout[OUT_BATCH_OFF + i]   = (float)batch[g];
}

// -------------------- 3) ball query: 33 nearest within r -------------------
#define BQ_TILE 2048
#define BQ_CAP  1024
__global__ void __launch_bounds__(256,1) ballquery_kernel(const float* __restrict__ pos) {
    extern __shared__ float sm[];
    float* Xs = sm; float* Ys = sm + BQ_TILE; float* Zs = sm + 2*BQ_TILE;
    ull* buf = (ull*)(sm + 3*BQ_TILE);
    int tid = threadIdx.x;
    int wid = tid >> 5, lane = tid & 31;
    int c = blockIdx.x*8 + wid;
    int cloud = c >> 12;
    const float* pcloud = pos + (size_t)cloud*NPTS*3;
    float cx = g_cent[3*c], cy = g_cent[3*c+1], cz = g_cent[3*c+2];
    ull* mybuf = buf + (size_t)wid*BQ_CAP;
    int cnt = 0;
    for (int tile = 0; tile < NPTS/BQ_TILE; ++tile) {
        for (int i = tid; i < BQ_TILE; i += 256) {
            int pidx = tile*BQ_TILE + i;
            Xs[i] = pcloud[3*pidx]; Ys[i] = pcloud[3*pidx+1]; Zs[i] = pcloud[3*pidx+2];
        }
        __syncthreads();
        for (int i = lane; i < BQ_TILE; i += 32) {
            float dx = Xs[i]-cx, dy = Ys[i]-cy, dz = Zs[i]-cz;
            float d2 = fmaf(dz,dz,fmaf(dy,dy,dx*dx));
            bool hit = (d2 <= R2CONST);
            unsigned m = __ballot_sync(0xffffffffu, hit);
            int pre = __popc(m & ((1u << lane) - 1u));
            if (hit) {
                int slot = cnt + pre;
                if (slot < BQ_CAP)
                    mybuf[slot] = ((ull)__float_as_uint(d2) << 32)
                                | (unsigned)(tile*BQ_TILE + i);
            }
            cnt += __popc(m);
        }
        __syncthreads();
    }
    if (cnt > BQ_CAP) cnt = BQ_CAP;
    int selfg = g_gidx[c];
    for (int it = 0; it < KNBR; ++it) {
        ull mn = ~0ull;
        for (int j = lane; j < cnt; j += 32) {
            ull v = mybuf[j];
            if (v < mn) mn = v;
        }
#pragma unroll
        for (int off = 16; off > 0; off >>= 1) {
            ull o = __shfl_down_sync(0xffffffffu, mn, off);
            if (o < mn) mn = o;
        }
        mn = __shfl_sync(0xffffffffu, mn, 0);
        int nbr;
        if (mn == ~0ull) {
            nbr = selfg;
        } else {
            nbr = cloud*NPTS + (int)(mn & 0xffffffffu);
            for (int j = lane; j < cnt; j += 32)
                if (mybuf[j] == mn) mybuf[j] = ~0ull;
        }
        if (lane == 0) g_nbr[c*KNBR + it] = nbr;
    }
}

// -------------------- 4) per-point layer-1 x-part --------------------------
__global__ void pfeat_kernel(const float* __restrict__ x,
                             const float* __restrict__ lw1,
                             const float* __restrict__ lb1) {
    int idx = blockIdx.x*blockDim.x + threadIdx.x;
    int p = idx >> 7, ch = idx & 127;
    float acc = lb1[ch];
    const float* xp = x + (size_t)p*CDIM;
#pragma unroll
    for (int j = 0; j < CDIM; j++)
        acc = fmaf(xp[j], lw1[j*H1DIM + ch], acc);
    g_A[(size_t)p*H1DIM + ch] = acc;
}

// -------------------- 5) per-edge layer-1 (warp per edge, float4) ----------
__global__ void eh1_kernel(const float* __restrict__ pos,
                           const float* __restrict__ lw1) {
    int idx = blockIdx.x*blockDim.x + threadIdx.x;   // NEDGE*32
    int e = idx >> 5, k4 = (idx & 31) * 4;
    int c = e / KNBR;
    int col = g_nbr[e];
    float dx = pos[3*col]   - g_cent[3*c];
    float dy = pos[3*col+1] - g_cent[3*c+1];
    float dz = pos[3*col+2] - g_cent[3*c+2];
    float4 a  = *(const float4*)(g_A + (size_t)col*H1DIM + k4);
    float4 wx = *(const float4*)(lw1 + 32*H1DIM + k4);
    float4 wy = *(const float4*)(lw1 + 33*H1DIM + k4);
    float4 wz = *(const float4*)(lw1 + 34*H1DIM + k4);
    float4 h;
    h.x = fmaxf(fmaf(dz, wz.x, fmaf(dy, wy.x, fmaf(dx, wx.x, a.x))), 0.f);
    h.y = fmaxf(fmaf(dz, wz.y, fmaf(dy, wy.y, fmaf(dx, wx.y, a.y))), 0.f);
    h.z = fmaxf(fmaf(dz, wz.z, fmaf(dy, wy.z, fmaf(dx, wx.z, a.z))), 0.f);
    h.w = fmaxf(fmaf(dz, wz.w, fmaf(dy, wy.w, fmaf(dx, wx.w, a.w))), 0.f);
    *(float4*)(g_H1 + (size_t)e*H1DIM + k4) = h;
}

// -------------------- 5b) zero the aggregate buffer ------------------------
__global__ void zeroagg_kernel() {
    int i = blockIdx.x*blockDim.x + threadIdx.x;     // NCENT*H2DIM/4 threads
    ((uint4*)g_agg)[i] = make_uint4(0u, 0u, 0u, 0u);
}

// -------------------- 6) SGEMM + fused segment-max epilogue ----------------
// C_bits[g*256+col] = max over rows in group g of relu(A@B + bias).
// relu >= 0 => uint bit pattern monotone => atomicMax(uint) == float max.
__global__ void __launch_bounds__(256) sgemm_fused_kernel(const float* __restrict__ A,
                                                          const float* __restrict__ Bw,
                                                          const float* __restrict__ bias) {
    __shared__ float As[8][128];
    __shared__ float Bs[8][128];
    int t = threadIdx.x;
    int tx = t & 15, ty = t >> 4;
    int m0 = blockIdx.x * 128, n0 = blockIdx.y * 128;
    float acc[8][8];
#pragma unroll
    for (int i = 0; i < 8; i++)
#pragma unroll
        for (int j = 0; j < 8; j++) acc[i][j] = 0.f;
    int r  = t >> 1, cc4 = (t & 1) * 4;
    int r2 = t >> 5, c2  = (t & 31) * 4;
    for (int k0 = 0; k0 < H1DIM; k0 += 8) {
        float4 av = *(const float4*)(A + (size_t)(m0 + r)*H1DIM + k0 + cc4);
        As[cc4+0][r] = av.x; As[cc4+1][r] = av.y; As[cc4+2][r] = av.z; As[cc4+3][r] = av.w;
        *(float4*)(&Bs[r2][c2]) = *(const float4*)(Bw + (size_t)(k0 + r2)*256 + n0 + c2);
        __syncthreads();
#pragma unroll
        for (int k = 0; k < 8; k++) {
            float4 a0 = *(const float4*)(&As[k][ty*8]);
            float4 a1 = *(const float4*)(&As[k][ty*8+4]);
            float4 b0 = *(const float4*)(&Bs[k][tx*8]);
            float4 b1 = *(const float4*)(&Bs[k][tx*8+4]);
            float a[8] = {a0.x,a0.y,a0.z,a0.w,a1.x,a1.y,a1.z,a1.w};
            float bb[8] = {b0.x,b0.y,b0.z,b0.w,b1.x,b1.y,b1.z,b1.w};
#pragma unroll
            for (int i = 0; i < 8; i++)
#pragma unroll
                for (int j = 0; j < 8; j++) acc[i][j] = fmaf(a[i], bb[j], acc[i][j]);
        }
        __syncthreads();
    }
#pragma unroll
    for (int i = 0; i < 8; i++) {
        int row = m0 + ty*8 + i;
        int g = row / KNBR;
#pragma unroll
        for (int j = 0; j < 8; j++) {
            int colI = n0 + tx*8 + j;
            float v = fmaxf(acc[i][j] + bias[colI], 0.f);
            atomicMax(&g_agg[(size_t)g*H2DIM + colI], __float_as_uint(v));
        }
    }
}

// -------------------- 7) plain SGEMM for the final layer -------------------
__global__ void __launch_bounds__(256) sgemm_kernel(const float* __restrict__ A,
                                                    const float* __restrict__ Bw,
                                                    const float* __restrict__ bias,
                                                    float* __restrict__ C,
                                                    int Kdim) {
    __shared__ float As[8][128];
    __shared__ float Bs[8][128];
    int t = threadIdx.x;
    int tx = t & 15, ty = t >> 4;
    int m0 = blockIdx.x * 128, n0 = blockIdx.y * 128;
    float acc[8][8];
#pragma unroll
    for (int i = 0; i < 8; i++)
#pragma unroll
        for (int j = 0; j < 8; j++) acc[i][j] = 0.f;
    int r  = t >> 1, cc4 = (t & 1) * 4;
    int r2 = t >> 5, c2  = (t & 31) * 4;
    for (int k0 = 0; k0 < Kdim; k0 += 8) {
        float4 av = *(const float4*)(A + (size_t)(m0 + r)*Kdim + k0 + cc4);
        As[cc4+0][r] = av.x; As[cc4+1][r] = av.y; As[cc4+2][r] = av.z; As[cc4+3][r] = av.w;
        *(float4*)(&Bs[r2][c2]) = *(const float4*)(Bw + (size_t)(k0 + r2)*256 + n0 + c2);
        __syncthreads();
#pragma unroll
        for (int k = 0; k < 8; k++) {
            float4 a0 = *(const float4*)(&As[k][ty*8]);
            float4 a1 = *(const float4*)(&As[k][ty*8+4]);
            float4 b0 = *(const float4*)(&Bs[k][tx*8]);
            float4 b1 = *(const float4*)(&Bs[k][tx*8+4]);
            float a[8] = {a0.x,a0.y,a0.z,a0.w,a1.x,a1.y,a1.z,a1.w};
            float bb[8] = {b0.x,b0.y,b0.z,b0.w,b1.x,b1.y,b1.z,b1.w};
#pragma unroll
            for (int i = 0; i < 8; i++)
#pragma unroll
                for (int j = 0; j < 8; j++) acc[i][j] = fmaf(a[i], bb[j], acc[i][j]);
        }
        __syncthreads();
    }
#pragma unroll
    for (int i = 0; i < 8; i++) {
        size_t row = (size_t)m0 + ty*8 + i;
#pragma unroll
        for (int j = 0; j < 8; j++) {
            int colI = n0 + tx*8 + j;
            float v = acc[i][j] + bias[colI];
            C[row*256 + colI] = fmaxf(v, 0.f);
        }
    }
}

// -------------------- launch ------------------------------------------------
extern "C" void kernel_launch(void* const* d_in, const int* in_sizes, int n_in,
                              void* d_out, int out_size) {
    const float* x     = (const float*)d_in[0];
    const float* pos   = (const float*)d_in[1];
    const int*   batch = (const int*)  d_in[2];
    const float* lw1   = (const float*)d_in[3];
    const float* lb1   = (const float*)d_in[4];
    const float* lw2   = (const float*)d_in[5];
    const float* lb2   = (const float*)d_in[6];
    const float* gw1   = (const float*)d_in[7];
    const float* gb1   = (const float*)d_in[8];
    float* dout = (float*)d_out;

    cudaFuncSetAttribute(fps_kernel, cudaFuncAttributeMaxDynamicSharedMemorySize,
                         FPS_SMEM);
    int bq_smem = 3*BQ_TILE*(int)sizeof(float) + 8*BQ_CAP*(int)sizeof(ull);
    cudaFuncSetAttribute(ballquery_kernel, cudaFuncAttributeMaxDynamicSharedMemorySize,
                         bq_smem);

    void *pH1 = nullptr, *pAgg = nullptr;
    cudaGetSymbolAddress(&pH1,  g_H1);
    cudaGetSymbolAddress(&pAgg, g_agg);

    fps_kernel<<<NB, 512, FPS_SMEM>>>(pos);
    gather_kernel<<<NCENT/256, 256>>>(pos, batch, dout);
    ballquery_kernel<<<NCENT/8, 256, bq_smem>>>(pos);
    pfeat_kernel<<<(NB*NPTS*H1DIM)/256, 256>>>(x, lw1, lb1);
    eh1_kernel<<<(NEDGE*32)/256, 256>>>(pos, lw1);
    zeroagg_kernel<<<(NCENT*H2DIM/4)/256, 256>>>();
    sgemm_fused_kernel<<<dim3(NEDGE/128, 2), 256>>>((const float*)pH1, lw2, lb2);
    sgemm_kernel<<<dim3(NCENT/128, 2), 256>>>((const float*)pAgg, gw1, gb1,
                                              dout, H2DIM);
}